// round 7
// baseline (speedup 1.0000x reference)
#include <cuda_runtime.h>
#include <cuda_bf16.h>
#include <cstdint>
#include <math.h>

#define NPIX  65536
#define WIMG  256
#define EPSN  1e-12f

// ---------------- scratch (device globals; no allocation allowed) -----------
__device__ float g_yv[8ull * 64 * 65536];          // 128 MB: v activations only
__device__ float g_G[8 * 8 * 8 * 8];               // [bz][head][c][d] gram
__device__ float g_nq[8 * 64];
__device__ float g_nk[8 * 64];
__device__ float g_M[8 * 64 * 64];                 // folded w_po @ attn

// ---------------- warp-level TF32 MMA (sm_80+ PTX) --------------------------
__device__ __forceinline__ uint32_t f2tf32(float f) {
    uint32_t u;
    asm("cvt.rna.tf32.f32 %0, %1;" : "=r"(u) : "f"(f));
    return u;
}
__device__ __forceinline__ void mma_tf32(float c[4],
                                         uint32_t a0, uint32_t a1,
                                         uint32_t a2, uint32_t a3,
                                         uint32_t b0, uint32_t b1) {
    asm volatile(
        "mma.sync.aligned.m16n8k8.row.col.f32.tf32.tf32.f32 "
        "{%0,%1,%2,%3}, {%4,%5,%6,%7}, {%8,%9}, {%0,%1,%2,%3};"
        : "+f"(c[0]), "+f"(c[1]), "+f"(c[2]), "+f"(c[3])
        : "r"(a0), "r"(a1), "r"(a2), "r"(a3), "r"(b0), "r"(b1));
}

// ---------------- K0: zero the global accumulators --------------------------
__global__ __launch_bounds__(256) void k0_zero() {
    int t = blockIdx.x * 256 + threadIdx.x;
    if (t < 4096) g_G[t] = 0.f;
    if (t < 512) { g_nq[t] = 0.f; g_nk[t] = 0.f; }
}

// ---------------- F1: fused qkv-1x1 (tensor core) + dw3x3(q,k) + gram + v ---
// grid (256 tiles, 8 bz); block 256 (8 warps).
// Tile 16x16 output px, halo 18x18 = 324 px (padded to 336 = 21 m-tiles).
// smem floats: ws 192*65 | xs 336*65 | ys 336*17 | qs 8*256 | ks 8*256 | wd 1728
#define WS_OFF 0
#define XS_OFF (192 * 65)                       // 12480
#define YS_OFF (XS_OFF + 336 * 65)              // 34320
#define QS_OFF (YS_OFF + 336 * 17)              // 40032
#define KS_OFF (QS_OFF + 2048)                  // 42080
#define WD_OFF (KS_OFF + 2048)                  // 44128
#define F1_FLOATS (WD_OFF + 1728)               // 45856
#define F1_SMEM (F1_FLOATS * 4)                 // 183424 B

__global__ __launch_bounds__(256) void f1_qkv_gram(const float* __restrict__ x,
                                                   const float* __restrict__ w1,
                                                   const float* __restrict__ w2,
                                                   const float* __restrict__ wdw1,
                                                   const float* __restrict__ wdw2) {
    extern __shared__ float sm[];
    uint32_t* ws = (uint32_t*)sm + WS_OFF;     // W tf32 bits [192][65]
    uint32_t* xs = (uint32_t*)sm + XS_OFF;     // x halo tf32 [336][65]
    float*    ys = sm + YS_OFF;                // y q,k  [336][17]
    float*    qs = sm + QS_OFF;
    float*    ks = sm + KS_OFF;
    float*    wd = sm + WD_OFF;                // dw weights [192][9]

    const int t = threadIdx.x, wid = t >> 5, lane = t & 31;
    const int gid = lane >> 2, tig = lane & 3;
    const int bz = blockIdx.y, br = bz >> 2, b = bz & 3;
    const int tile = blockIdx.x;
    const int ty = tile >> 4, tx = tile & 15;
    const int r0t = ty * 16, c0t = tx * 16;

    const float* W   = br ? w2 : w1;                              // [192][64]
    const float* wdw = br ? wdw2 : wdw1;                          // [192][9]
    const float* xb  = x + (size_t)(b * 128 + br * 64) * NPIX;    // [64][N]
    float*       vo  = g_yv + (size_t)bz * 64 * NPIX;             // [64][N]

    // --- load weights (tf32) and dw weights ---
    for (int i = t; i < 192 * 64; i += 256) {
        int oc = i >> 6, ic = i & 63;
        ws[oc * 65 + ic] = f2tf32(W[i]);
    }
    for (int i = t; i < 1728; i += 256) wd[i] = wdw[i];

    // --- load x halo (zero outside image): xs[hp][ic], transposed ---
    for (int ic = 0; ic < 64; ++ic) {
        const float* xc = xb + (size_t)ic * NPIX;
        for (int hp = t; hp < 324; hp += 256) {
            int ly = hp / 18, lx = hp - ly * 18;
            int gy = r0t + ly - 1, gx = c0t + lx - 1;
            float v = 0.f;
            if ((unsigned)gy < 256u && (unsigned)gx < 256u)
                v = xc[gy * WIMG + gx];
            xs[hp * 65 + ic] = f2tf32(v);
        }
    }
    for (int i = t; i < 12 * 65; i += 256) xs[324 * 65 + i] = 0u;  // pad rows
    __syncthreads();

    // --- per head: MMA q,k on halo -> conv -> gram ---
    for (int h = 0; h < 8; ++h) {
        for (int mt = wid; mt < 21; mt += 8) {
            const int ra = mt * 16 + gid, rb = ra + 8;
            uint32_t a[8][4];
#pragma unroll
            for (int kk = 0; kk < 8; ++kk) {
                a[kk][0] = xs[ra * 65 + kk * 8 + tig];
                a[kk][1] = xs[rb * 65 + kk * 8 + tig];
                a[kk][2] = xs[ra * 65 + kk * 8 + tig + 4];
                a[kk][3] = xs[rb * 65 + kk * 8 + tig + 4];
            }
            float accq[4] = {}, acck[4] = {};
            const int rq = (h * 8 + gid) * 65, rk = (64 + h * 8 + gid) * 65;
#pragma unroll
            for (int kk = 0; kk < 8; ++kk) {
                mma_tf32(accq, a[kk][0], a[kk][1], a[kk][2], a[kk][3],
                         ws[rq + kk * 8 + tig], ws[rq + kk * 8 + tig + 4]);
                mma_tf32(acck, a[kk][0], a[kk][1], a[kk][2], a[kk][3],
                         ws[rk + kk * 8 + tig], ws[rk + kk * 8 + tig + 4]);
            }
            const int ca = tig * 2;
            ys[ra * 17 + ca]     = accq[0];  ys[ra * 17 + ca + 1]     = accq[1];
            ys[rb * 17 + ca]     = accq[2];  ys[rb * 17 + ca + 1]     = accq[3];
            ys[ra * 17 + 8 + ca] = acck[0];  ys[ra * 17 + 8 + ca + 1] = acck[1];
            ys[rb * 17 + 8 + ca] = acck[2];  ys[rb * 17 + 8 + ca + 1] = acck[3];
        }
        __syncthreads();

        {   // dw conv 3x3 on q,k; one interior pixel per thread
            const int iy = t >> 4, ix = t & 15;
#pragma unroll
            for (int c = 0; c < 8; ++c) {
                const float* wq = wd + (h * 8 + c) * 9;
                const float* wk = wd + (64 + h * 8 + c) * 9;
                float sq = 0.f, sk = 0.f;
#pragma unroll
                for (int ky = 0; ky < 3; ++ky)
#pragma unroll
                    for (int kx = 0; kx < 3; ++kx) {
                        const int hp = (iy + ky) * 18 + ix + kx;
                        sq += ys[hp * 17 + c]     * wq[ky * 3 + kx];
                        sk += ys[hp * 17 + 8 + c] * wk[ky * 3 + kx];
                    }
                qs[c * 256 + t] = sq;
                ks[c * 256 + t] = sk;
            }
        }
        __syncthreads();

        for (int e = wid; e < 80; e += 8) {   // 64 gram + 8 nq + 8 nk
            float s = 0.f;
            if (e < 64) {
                int c = e >> 3, d = e & 7;
#pragma unroll
                for (int j = 0; j < 8; ++j)
                    s += qs[c * 256 + lane + 32 * j] * ks[d * 256 + lane + 32 * j];
            } else if (e < 72) {
                int c = e - 64;
#pragma unroll
                for (int j = 0; j < 8; ++j) {
                    float v = qs[c * 256 + lane + 32 * j]; s += v * v;
                }
            } else {
                int c = e - 72;
#pragma unroll
                for (int j = 0; j < 8; ++j) {
                    float v = ks[c * 256 + lane + 32 * j]; s += v * v;
                }
            }
#pragma unroll
            for (int off = 16; off; off >>= 1)
                s += __shfl_xor_sync(0xffffffffu, s, off);
            if (lane == 0) {
                if (e < 64)      atomicAdd(&g_G[bz * 512 + h * 64 + e], s);
                else if (e < 72) atomicAdd(&g_nq[bz * 64 + h * 8 + (e - 64)], s);
                else             atomicAdd(&g_nk[bz * 64 + h * 8 + (e - 72)], s);
            }
        }
        __syncthreads();
    }

    // --- v phase: MMA 64 v channels, store interior pixels only ---
    for (int mt = wid; mt < 21; mt += 8) {
        const int ra = mt * 16 + gid, rb = ra + 8;
        uint32_t a[8][4];
#pragma unroll
        for (int kk = 0; kk < 8; ++kk) {
            a[kk][0] = xs[ra * 65 + kk * 8 + tig];
            a[kk][1] = xs[rb * 65 + kk * 8 + tig];
            a[kk][2] = xs[ra * 65 + kk * 8 + tig + 4];
            a[kk][3] = xs[rb * 65 + kk * 8 + tig + 4];
        }
        const int lya = ra / 18, lxa = ra - lya * 18;
        const int lyb = rb / 18, lxb = rb - lyb * 18;
        const bool va = (lya >= 1 && lya <= 16 && lxa >= 1 && lxa <= 16);
        const bool vb = (lyb >= 1 && lyb <= 16 && lxb >= 1 && lxb <= 16);
        const size_t gpa = (size_t)(r0t + lya - 1) * WIMG + (c0t + lxa - 1);
        const size_t gpb = (size_t)(r0t + lyb - 1) * WIMG + (c0t + lxb - 1);
#pragma unroll
        for (int jn = 0; jn < 8; ++jn) {
            float acc[4] = {};
            const int rv = (128 + jn * 8 + gid) * 65;
#pragma unroll
            for (int kk = 0; kk < 8; ++kk)
                mma_tf32(acc, a[kk][0], a[kk][1], a[kk][2], a[kk][3],
                         ws[rv + kk * 8 + tig], ws[rv + kk * 8 + tig + 4]);
            const int ch = jn * 8 + tig * 2;
            if (va) {
                vo[(size_t)ch * NPIX + gpa]       = acc[0];
                vo[(size_t)(ch + 1) * NPIX + gpa] = acc[1];
            }
            if (vb) {
                vo[(size_t)ch * NPIX + gpb]       = acc[2];
                vo[(size_t)(ch + 1) * NPIX + gpb] = acc[3];
            }
        }
    }
}

// ---------------- K3: attn softmax + fold M = w_po @ attn -------------------
__global__ __launch_bounds__(256) void k3_attn(const float* __restrict__ wpo1,
                                               const float* __restrict__ wpo2,
                                               const float* __restrict__ t1,
                                               const float* __restrict__ t2) {
    __shared__ float attn[64 * 8];
    __shared__ float qn[64], kn[64];
    const int bz = blockIdx.x;
    const int br = bz >> 2;
    const int t  = threadIdx.x;

    if (t < 64) {
        qn[t] = fmaxf(sqrtf(g_nq[bz * 64 + t]), EPSN);
        kn[t] = fmaxf(sqrtf(g_nk[bz * 64 + t]), EPSN);
    }
    __syncthreads();
    if (t < 64) {
        int h = t >> 3;
        float tv = (br ? t2 : t1)[h];
        float L[8], mx = -1e30f;
#pragma unroll
        for (int d = 0; d < 8; ++d) {
            L[d] = g_G[bz * 512 + t * 8 + d] / (qn[t] * kn[h * 8 + d]) * tv;
            mx = fmaxf(mx, L[d]);
        }
        float ssum = 0.f;
#pragma unroll
        for (int d = 0; d < 8; ++d) { L[d] = expf(L[d] - mx); ssum += L[d]; }
        float inv = 1.f / ssum;
#pragma unroll
        for (int d = 0; d < 8; ++d) attn[t * 8 + d] = L[d] * inv;
    }
    __syncthreads();
    const float* wpo = br ? wpo2 : wpo1;
    for (int i = t; i < 4096; i += 256) {
        int o = i >> 6, col = i & 63;
        int h = col >> 3, d = col & 7;
        float m = 0.f;
#pragma unroll
        for (int c = 0; c < 8; ++c)
            m += wpo[o * 64 + h * 8 + c] * attn[(h * 8 + c) * 8 + d];
        g_M[bz * 4096 + i] = m;
    }
}

// ---------------- K4: out = M @ dw3x3(v_otherbranch) ------------------------
__global__ __launch_bounds__(256) void k4_out(const float* __restrict__ wdw1,
                                              const float* __restrict__ wdw2,
                                              float* __restrict__ out) {
    extern __shared__ float sm[];
    float* ys = sm;                  // [64][324]
    float* vs = ys + 64 * 324;       // [64][256]
    float* Ms = vs + 64 * 256;       // [j][o] transposed
    __shared__ float wdws[64 * 9];

    const int t     = threadIdx.x;
    const int bz    = blockIdx.y;
    const int brout = bz >> 2, b = bz & 3;
    const int vbr   = 1 - brout;
    const int tile  = blockIdx.x;
    const int ty = tile >> 4, tx = tile & 15;
    const int r0 = ty * 16, c0 = tx * 16;

    const float* wdw = (vbr ? wdw2 : wdw1) + 128 * 9;
    const float* yv  = g_yv + (size_t)(vbr * 4 + b) * 64 * NPIX;
    const float* Mg  = g_M + (size_t)bz * 4096;

    for (int i = t; i < 4096; i += 256) {
        int j = i >> 6, o = i & 63;
        Ms[i] = Mg[o * 64 + j];
    }
    for (int i = t; i < 576; i += 256) wdws[i] = wdw[i];

#pragma unroll 2
    for (int ch = 0; ch < 64; ++ch) {
        const float* yc = yv + (size_t)ch * NPIX;
        for (int hp = t; hp < 324; hp += 256) {
            int row = hp / 18;
            int hy = r0 + row - 1;
            int hx = c0 + (hp - row * 18) - 1;
            float v = 0.f;
            if ((unsigned)hy < 256u && (unsigned)hx < 256u)
                v = yc[hy * WIMG + hx];
            ys[ch * 324 + hp] = v;
        }
    }
    __syncthreads();
    {
        const int iy = t >> 4, ix = t & 15;
#pragma unroll 4
        for (int ch = 0; ch < 64; ++ch) {
            float s = 0.f;
#pragma unroll
            for (int ky = 0; ky < 3; ++ky)
#pragma unroll
                for (int kx = 0; kx < 3; ++kx)
                    s += ys[ch * 324 + (iy + ky) * 18 + ix + kx] *
                         wdws[ch * 9 + ky * 3 + kx];
            vs[ch * 256 + t] = s;
        }
    }
    __syncthreads();

    const int pix = t & 63, og = t >> 6, o0 = og * 16;
    float acc[16][4];
#pragma unroll
    for (int i = 0; i < 16; i++)
#pragma unroll
        for (int j = 0; j < 4; j++) acc[i][j] = 0.f;

#pragma unroll 8
    for (int j = 0; j < 64; ++j) {
        float4 v4 = *(float4*)&vs[j * 256 + pix * 4];
#pragma unroll
        for (int oq = 0; oq < 4; ++oq) {
            float4 m = *(float4*)&Ms[j * 64 + o0 + oq * 4];
            float mm[4] = {m.x, m.y, m.z, m.w};
#pragma unroll
            for (int r = 0; r < 4; ++r) {
                acc[oq * 4 + r][0] += mm[r] * v4.x;
                acc[oq * 4 + r][1] += mm[r] * v4.y;
                acc[oq * 4 + r][2] += mm[r] * v4.z;
                acc[oq * 4 + r][3] += mm[r] * v4.w;
            }
        }
    }
    const int p0 = pix * 4;
    const int py = p0 >> 4, px = p0 & 15;
    const size_t nb = (size_t)(r0 + py) * WIMG + c0 + px;
#pragma unroll
    for (int oo = 0; oo < 16; ++oo) {
        float4 v = make_float4(acc[oo][0], acc[oo][1], acc[oo][2], acc[oo][3]);
        *(float4*)&out[(size_t)(b * 128 + brout * 64 + o0 + oo) * NPIX + nb] = v;
    }
}

// ---------------- launch ----------------------------------------------------
extern "C" void kernel_launch(void* const* d_in, const int* in_sizes, int n_in,
                              void* d_out, int out_size) {
    const float* x      = (const float*)d_in[0];
    const float* w_qkv1 = (const float*)d_in[1];
    const float* w_qkv2 = (const float*)d_in[2];
    const float* w_dw1  = (const float*)d_in[3];
    const float* w_dw2  = (const float*)d_in[4];
    const float* w_po1  = (const float*)d_in[5];
    const float* w_po2  = (const float*)d_in[6];
    const float* t1     = (const float*)d_in[7];
    const float* t2     = (const float*)d_in[8];
    float* out = (float*)d_out;

    const int K4_SMEM = (64 * 324 + 64 * 256 + 64 * 64) * 4;        // 164864
    cudaFuncSetAttribute(f1_qkv_gram, cudaFuncAttributeMaxDynamicSharedMemorySize, F1_SMEM);
    cudaFuncSetAttribute(k4_out, cudaFuncAttributeMaxDynamicSharedMemorySize, K4_SMEM);

    k0_zero<<<16, 256>>>();
    f1_qkv_gram<<<dim3(256, 8), 256, F1_SMEM>>>(x, w_qkv1, w_qkv2, w_dw1, w_dw2);
    k3_attn<<<8, 256>>>(w_po1, w_po2, t1, t2);
    k4_out<<<dim3(256, 8), 256, K4_SMEM>>>(w_dw1, w_dw2, out);
}

// round 9
// speedup vs baseline: 2.6729x; 2.6729x over previous
#include <cuda_runtime.h>
#include <cuda_bf16.h>
#include <cstdint>
#include <math.h>

#define NPIX  65536
#define WIMG  256
#define EPSN  1e-12f

// ---------------- scratch (device globals; no allocation allowed) -----------
__device__ float g_y[8ull * 192 * 65536];          // 384 MB qkv activations
__device__ float g_G[8 * 8 * 8 * 8];               // [bz][head][c][d] gram
__device__ float g_nq[8 * 64];
__device__ float g_nk[8 * 64];
__device__ float g_M[8 * 64 * 64];                 // folded w_po @ attn [o][j]

// ---------------- warp-level TF32 MMA (sm_80+ PTX) --------------------------
__device__ __forceinline__ uint32_t f2tf32(float f) {
    uint32_t u;
    asm("cvt.rna.tf32.f32 %0, %1;" : "=r"(u) : "f"(f));
    return u;
}
__device__ __forceinline__ void mma_tf32(float c[4],
                                         uint32_t a0, uint32_t a1,
                                         uint32_t a2, uint32_t a3,
                                         uint32_t b0, uint32_t b1) {
    asm volatile(
        "mma.sync.aligned.m16n8k8.row.col.f32.tf32.tf32.f32 "
        "{%0,%1,%2,%3}, {%4,%5,%6,%7}, {%8,%9}, {%0,%1,%2,%3};"
        : "+f"(c[0]), "+f"(c[1]), "+f"(c[2]), "+f"(c[3])
        : "r"(a0), "r"(a1), "r"(a2), "r"(a3), "r"(b0), "r"(b1));
}

// ---------------- K0: zero the global accumulators --------------------------
__global__ __launch_bounds__(256) void k0_zero() {
    int t = blockIdx.x * 256 + threadIdx.x;
    if (t < 4096) g_G[t] = 0.f;
    if (t < 512) { g_nq[t] = 0.f; g_nk[t] = 0.f; }
}

// ---------------- K1: y = W_qkv @ x via tensor-core TF32 mma ---------------
#define XS_STRIDE 65
__global__ __launch_bounds__(256) void k1_qkv_mma(const float* __restrict__ x,
                                                  const float* __restrict__ w1,
                                                  const float* __restrict__ w2) {
    __shared__ uint32_t xs[128 * XS_STRIDE];   // 33.3 KB, tf32-rounded bits
    const int t = threadIdx.x, wid = t >> 5, lane = t & 31;
    const int gid = lane >> 2, tig = lane & 3;
    const int bz = blockIdx.y, br = bz >> 2, b = bz & 3;
    const float* W  = br ? w2 : w1;                              // [192][64]
    const float* xb = x + (size_t)(b * 128 + br * 64) * NPIX;    // [64][N]
    float*       yb = g_y + (size_t)bz * 192 * NPIX;             // [192][N]
    const int n0 = blockIdx.x * 128;
    const int ocbase = wid * 24;

    uint32_t bf[3][8][2];
#pragma unroll
    for (int j = 0; j < 3; ++j) {
        const int oc = ocbase + j * 8 + gid;
#pragma unroll
        for (int k = 0; k < 8; ++k) {
            bf[j][k][0] = f2tf32(W[oc * 64 + k * 8 + tig]);
            bf[j][k][1] = f2tf32(W[oc * 64 + k * 8 + tig + 4]);
        }
    }

    for (int i = t; i < 64 * 32; i += 256) {
        const int ic = i >> 5, f = i & 31;
        float4 v = *(const float4*)(xb + (size_t)ic * NPIX + n0 + f * 4);
        const int px = f * 4;
        xs[(px + 0) * XS_STRIDE + ic] = f2tf32(v.x);
        xs[(px + 1) * XS_STRIDE + ic] = f2tf32(v.y);
        xs[(px + 2) * XS_STRIDE + ic] = f2tf32(v.z);
        xs[(px + 3) * XS_STRIDE + ic] = f2tf32(v.w);
    }
    __syncthreads();

#pragma unroll
    for (int m = 0; m < 8; ++m) {
        float acc[3][4] = {};
        const int r0 = m * 16 + gid;
#pragma unroll
        for (int k = 0; k < 8; ++k) {
            const uint32_t a0 = xs[r0 * XS_STRIDE + k * 8 + tig];
            const uint32_t a1 = xs[(r0 + 8) * XS_STRIDE + k * 8 + tig];
            const uint32_t a2 = xs[r0 * XS_STRIDE + k * 8 + tig + 4];
            const uint32_t a3 = xs[(r0 + 8) * XS_STRIDE + k * 8 + tig + 4];
#pragma unroll
            for (int j = 0; j < 3; ++j)
                mma_tf32(acc[j], a0, a1, a2, a3, bf[j][k][0], bf[j][k][1]);
        }
#pragma unroll
        for (int j = 0; j < 3; ++j) {
            const int col = ocbase + j * 8 + tig * 2;
            yb[(size_t)col * NPIX + n0 + r0]           = acc[j][0];
            yb[(size_t)(col + 1) * NPIX + n0 + r0]     = acc[j][1];
            yb[(size_t)col * NPIX + n0 + r0 + 8]       = acc[j][2];
            yb[(size_t)(col + 1) * NPIX + n0 + r0 + 8] = acc[j][3];
        }
    }
}

// ---------------- K2: depthwise 3x3 on q,k + gram / norm reductions ---------
__global__ __launch_bounds__(256) void k2_dw_gram(const float* __restrict__ wdw1,
                                                  const float* __restrict__ wdw2) {
    __shared__ float ys[16 * 324];
    __shared__ float qs[8 * 256];
    __shared__ float ks[8 * 256];
    __shared__ float wdws[16 * 9];

    const int t    = threadIdx.x;
    const int tile = blockIdx.x;
    const int h    = blockIdx.y;
    const int bz   = blockIdx.z;
    const int br   = bz >> 2;
    const int ty = tile >> 4, tx = tile & 15;
    const int r0 = ty * 16, c0 = tx * 16;

    const float* ybase = g_y + (size_t)bz * 192 * NPIX;
    const float* wdw   = br ? wdw2 : wdw1;

    if (t < 144) {
        int ch = t / 9, kk = t - ch * 9;
        int cg = (ch < 8) ? (h * 8 + ch) : (64 + h * 8 + (ch - 8));
        wdws[ch * 9 + kk] = wdw[cg * 9 + kk];
    }
#pragma unroll
    for (int ch = 0; ch < 16; ++ch) {
        int cg = (ch < 8) ? (h * 8 + ch) : (64 + h * 8 + (ch - 8));
        const float* yc = ybase + (size_t)cg * NPIX;
        for (int hp = t; hp < 324; hp += 256) {
            int row = hp / 18;
            int hy = r0 + row - 1;
            int hx = c0 + (hp - row * 18) - 1;
            float v = 0.f;
            if ((unsigned)hy < 256u && (unsigned)hx < 256u)
                v = yc[hy * WIMG + hx];
            ys[ch * 324 + hp] = v;
        }
    }
    __syncthreads();

    {
        const int iy = t >> 4, ix = t & 15;
#pragma unroll
        for (int ch = 0; ch < 16; ++ch) {
            float s = 0.f;
#pragma unroll
            for (int ky = 0; ky < 3; ++ky)
#pragma unroll
                for (int kx = 0; kx < 3; ++kx)
                    s += ys[ch * 324 + (iy + ky) * 18 + ix + kx] *
                         wdws[ch * 9 + ky * 3 + kx];
            if (ch < 8) qs[ch * 256 + t] = s;
            else        ks[(ch - 8) * 256 + t] = s;
        }
    }
    __syncthreads();

    const int wid = t >> 5, lane = t & 31;
    for (int e = wid; e < 80; e += 8) {
        float s = 0.f;
        if (e < 64) {
            int c = e >> 3, d = e & 7;
#pragma unroll
            for (int j = 0; j < 8; ++j)
                s += qs[c * 256 + lane + 32 * j] * ks[d * 256 + lane + 32 * j];
        } else if (e < 72) {
            int c = e - 64;
#pragma unroll
            for (int j = 0; j < 8; ++j) {
                float v = qs[c * 256 + lane + 32 * j]; s += v * v;
            }
        } else {
            int c = e - 72;
#pragma unroll
            for (int j = 0; j < 8; ++j) {
                float v = ks[c * 256 + lane + 32 * j]; s += v * v;
            }
        }
#pragma unroll
        for (int off = 16; off; off >>= 1)
            s += __shfl_xor_sync(0xffffffffu, s, off);
        if (lane == 0) {
            if (e < 64)       atomicAdd(&g_G[bz * 512 + h * 64 + (e >> 3) * 8 + (e & 7)], s);
            else if (e < 72)  atomicAdd(&g_nq[bz * 64 + h * 8 + (e - 64)], s);
            else              atomicAdd(&g_nk[bz * 64 + h * 8 + (e - 72)], s);
        }
    }
}

// ---------------- K3: attn softmax + fold M = w_po @ attn -------------------
__global__ __launch_bounds__(256) void k3_attn(const float* __restrict__ wpo1,
                                               const float* __restrict__ wpo2,
                                               const float* __restrict__ t1,
                                               const float* __restrict__ t2) {
    __shared__ float attn[64 * 8];
    __shared__ float qn[64], kn[64];
    const int bz = blockIdx.x;
    const int br = bz >> 2;
    const int t  = threadIdx.x;

    if (t < 64) {
        qn[t] = fmaxf(sqrtf(g_nq[bz * 64 + t]), EPSN);
        kn[t] = fmaxf(sqrtf(g_nk[bz * 64 + t]), EPSN);
    }
    __syncthreads();
    if (t < 64) {
        int h = t >> 3;
        float tv = (br ? t2 : t1)[h];
        float L[8], mx = -1e30f;
#pragma unroll
        for (int d = 0; d < 8; ++d) {
            L[d] = g_G[bz * 512 + t * 8 + d] / (qn[t] * kn[h * 8 + d]) * tv;
            mx = fmaxf(mx, L[d]);
        }
        float ssum = 0.f;
#pragma unroll
        for (int d = 0; d < 8; ++d) { L[d] = expf(L[d] - mx); ssum += L[d]; }
        float inv = 1.f / ssum;
#pragma unroll
        for (int d = 0; d < 8; ++d) attn[t * 8 + d] = L[d] * inv;
    }
    __syncthreads();
    const float* wpo = br ? wpo2 : wpo1;
    for (int i = t; i < 4096; i += 256) {
        int o = i >> 6, col = i & 63;
        int h = col >> 3, d = col & 7;
        float m = 0.f;
#pragma unroll
        for (int c = 0; c < 8; ++c)
            m += wpo[o * 64 + h * 8 + c] * attn[(h * 8 + c) * 8 + d];
        g_M[bz * 4096 + i] = m;   // [o][j]
    }
}

// ---------------- K4b: out = M @ dw3x3(v) — chunked halo + tensor core ------
// grid (256 tiles, 8 = brout*4+b); block 256 (8 warps).
// smem words: vst [256 px][68] tf32 | ys8 [8][324] | wd [576]  = 82304 B
#define K4B_VST 0
#define K4B_YS  (256 * 68)                 // 17408
#define K4B_WD  (K4B_YS + 8 * 324)         // 20000
#define K4B_WORDS (K4B_WD + 576)           // 20576
#define K4B_SMEM (K4B_WORDS * 4)           // 82304 B

__global__ __launch_bounds__(256) void k4_out(const float* __restrict__ wdw1,
                                              const float* __restrict__ wdw2,
                                              float* __restrict__ out) {
    extern __shared__ float sm[];
    uint32_t* vst = (uint32_t*)sm + K4B_VST;   // conv(v) tf32 [px][j], stride 68
    float*    ys8 = sm + K4B_YS;               // 8-channel halo chunk
    float*    wd  = sm + K4B_WD;               // dw weights, v part [64][9]

    const int t = threadIdx.x, wid = t >> 5, lane = t & 31;
    const int gid = lane >> 2, tig = lane & 3;
    const int bz = blockIdx.y;
    const int brout = bz >> 2, b = bz & 3;
    const int vbr = 1 - brout;                 // cross-branch V swap
    const int tile = blockIdx.x;
    const int ty = tile >> 4, tx = tile & 15;
    const int r0 = ty * 16, c0 = tx * 16;

    const float* wdw = (vbr ? wdw2 : wdw1) + 128 * 9;                 // v part
    const float* yv  = g_y + (size_t)((vbr * 4 + b) * 192 + 128) * NPIX;
    const float* Mg  = g_M + (size_t)bz * 4096;                       // [o][j]

    for (int i = t; i < 576; i += 256) wd[i] = wdw[i];

    // --- dwconv in chunks of 8 channels; results -> vst (tf32) ---
    const int iy = t >> 4, ix = t & 15;
    for (int cc = 0; cc < 8; ++cc) {
        __syncthreads();                       // protect ys8 reuse
        for (int i = t; i < 8 * 324; i += 256) {
            const int c = i / 324, hp = i - c * 324;
            const int row = hp / 18;
            const int hy = r0 + row - 1;
            const int hx = c0 + (hp - row * 18) - 1;
            float v = 0.f;
            if ((unsigned)hy < 256u && (unsigned)hx < 256u)
                v = yv[(size_t)(cc * 8 + c) * NPIX + hy * WIMG + hx];
            ys8[i] = v;
        }
        __syncthreads();
#pragma unroll
        for (int c = 0; c < 8; ++c) {
            const float* w9 = wd + (cc * 8 + c) * 9;
            float s = 0.f;
#pragma unroll
            for (int ky = 0; ky < 3; ++ky)
#pragma unroll
                for (int kx = 0; kx < 3; ++kx)
                    s += ys8[c * 324 + (iy + ky) * 18 + ix + kx] * w9[ky * 3 + kx];
            vst[t * 68 + cc * 8 + c] = f2tf32(s);
        }
    }
    __syncthreads();

    // --- GEMM: D[256 px][64 oc] = vst[px][j] @ M[oc][j]^T via mma ---
    const int ocb = wid * 8;
    uint32_t bfm[8][2];
#pragma unroll
    for (int jc = 0; jc < 8; ++jc) {
        bfm[jc][0] = f2tf32(Mg[(ocb + gid) * 64 + jc * 8 + tig]);
        bfm[jc][1] = f2tf32(Mg[(ocb + gid) * 64 + jc * 8 + tig + 4]);
    }
    const size_t obase = (size_t)(b * 128 + brout * 64) * NPIX;
#pragma unroll
    for (int mt = 0; mt < 16; ++mt) {
        float acc[4] = {};
#pragma unroll
        for (int jc = 0; jc < 8; ++jc) {
            const uint32_t a0 = vst[(mt * 16 + gid) * 68 + jc * 8 + tig];
            const uint32_t a1 = vst[(mt * 16 + gid + 8) * 68 + jc * 8 + tig];
            const uint32_t a2 = vst[(mt * 16 + gid) * 68 + jc * 8 + tig + 4];
            const uint32_t a3 = vst[(mt * 16 + gid + 8) * 68 + jc * 8 + tig + 4];
            mma_tf32(acc, a0, a1, a2, a3, bfm[jc][0], bfm[jc][1]);
        }
        // D rows: px = mt*16+gid (row mt, col gid) and +8 ; cols: oc = ocb+tig*2(+1)
        const size_t ga = (size_t)(r0 + mt) * WIMG + c0 + gid;
        const int oc = ocb + tig * 2;
        out[obase + (size_t)oc * NPIX + ga]           = acc[0];
        out[obase + (size_t)(oc + 1) * NPIX + ga]     = acc[1];
        out[obase + (size_t)oc * NPIX + ga + 8]       = acc[2];
        out[obase + (size_t)(oc + 1) * NPIX + ga + 8] = acc[3];
    }
}

// ---------------- launch ----------------------------------------------------
extern "C" void kernel_launch(void* const* d_in, const int* in_sizes, int n_in,
                              void* d_out, int out_size) {
    const float* x      = (const float*)d_in[0];
    const float* w_qkv1 = (const float*)d_in[1];
    const float* w_qkv2 = (const float*)d_in[2];
    const float* w_dw1  = (const float*)d_in[3];
    const float* w_dw2  = (const float*)d_in[4];
    const float* w_po1  = (const float*)d_in[5];
    const float* w_po2  = (const float*)d_in[6];
    const float* t1     = (const float*)d_in[7];
    const float* t2     = (const float*)d_in[8];
    float* out = (float*)d_out;

    cudaFuncSetAttribute(k4_out, cudaFuncAttributeMaxDynamicSharedMemorySize, K4B_SMEM);

    k0_zero<<<16, 256>>>();
    k1_qkv_mma<<<dim3(512, 8), 256>>>(x, w_qkv1, w_qkv2);
    k2_dw_gram<<<dim3(256, 8, 8), 256>>>(w_dw1, w_dw2);
    k3_attn<<<8, 256>>>(w_po1, w_po2, t1, t2);
    k4_out<<<dim3(256, 8), 256, K4B_SMEM>>>(w_dw1, w_dw2, out);
}